// round 15
// baseline (speedup 1.0000x reference)
#include <cuda_runtime.h>
#include <cuda_fp16.h>

#define Bq 4
#define Cc 32
#define Tt 1024
#define Uu 32
#define Hh 128
#define NCHK 4                  // 256-j chunks

// Scratch — device globals (no allocations allowed).
__device__ float    g_qp[Bq * Tt * Uu];            // q + bh, (B,T,U) f32
__device__ unsigned g_kh_u[Bq * Uu * Tt / 2];      // k as f16, (B,U,T)
__device__ unsigned g_xh_u[Bq * Cc * Tt / 2];      // x as f16, (B,C,T)

__device__ __forceinline__ __half2 tanh2(__half2 x) {
    unsigned xi = *reinterpret_cast<unsigned*>(&x), ri;
    asm("tanh.approx.f16x2 %0, %1;" : "=r"(ri) : "r"(xi));
    return *reinterpret_cast<__half2*>(&ri);
}
__device__ __forceinline__ __half2 u2h2(unsigned u) { return *reinterpret_cast<__half2*>(&u); }
__device__ __forceinline__ unsigned h22u(__half2 h) { return *reinterpret_cast<unsigned*>(&h); }

// ---------------------------------------------------------------------------
// k_prep (R8, proven): 8 tokens/block, grid = B*(T/8) = 512, 256 threads.
// ---------------------------------------------------------------------------
__global__ void __launch_bounds__(256) k_prep(const float* __restrict__ x,
                                              const float* __restrict__ Wt,
                                              const float* __restrict__ Wx,
                                              const float* __restrict__ bh) {
    __shared__ float xs[Cc][9];
    __shared__ float Wts[Cc][33];
    __shared__ float Wxs[Cc][33];
    __shared__ float bhs[Uu];
    __shared__ __half kts[Uu][10];

    int b  = blockIdx.x >> 7;
    int t0 = (blockIdx.x & 127) * 8;
    int tid = threadIdx.x, w = tid >> 5, lane = tid & 31;

    {
        int c = tid >> 3, tl = tid & 7;
        xs[c][tl] = x[(size_t)b * Cc * Tt + (size_t)c * Tt + t0 + tl];
    }
    for (int i = tid; i < Cc * Uu; i += 256) {
        int c = i >> 5, u = i & 31;
        Wts[c][u] = Wt[i];
        Wxs[c][u] = Wx[i];
    }
    if (tid < Uu) bhs[tid] = bh[tid];
    __syncthreads();

    {
        int tl = w, u = lane;
        float accq = bhs[u], acck = 0.f;
        #pragma unroll
        for (int c = 0; c < Cc; c++) {
            float xv = xs[c][tl];
            accq += xv * Wts[c][u];
            acck += xv * Wxs[c][u];
        }
        g_qp[((size_t)b * Tt + t0 + tl) * Uu + u] = accq;
        kts[u][tl] = __float2half(acck);
    }
    __syncthreads();

    if (tid < 128) {
        int r = tid >> 2, g = tid & 3;
        __half* kh = (__half*)g_kh_u;
        __half2 kv = __halves2half2(kts[r][2 * g], kts[r][2 * g + 1]);
        *(unsigned*)(kh + ((size_t)b * Uu + r) * Tt + t0 + 2 * g) = h22u(kv);
        __half* xh = (__half*)g_xh_u;
        __half2 xv = __floats2half2_rn(xs[r][2 * g], xs[r][2 * g + 1]);
        *(unsigned*)(xh + ((size_t)b * Cc + r) * Tt + t0 + 2 * g) = h22u(xv);
    }
}

// ---------------------------------------------------------------------------
// k_fused: 8 rows/block, 128 threads, warp w owns rows 2w, 2w+1.
// Phase A: hybrid tanh scores -> es. p-pass: exp in place. a-write.
// Phase B: v = p @ x^T via mma.sync (HMMA) -> vsh (f32). LN1+FF+LN2.
// ---------------------------------------------------------------------------
#define OFF_K    0                           // half2 khs/x-tile[32][128] 16384 | W1T overlay
#define OFF_E    16384                       // half2 es[8][512]  16384 (e then p) | W2p overlay tail
#define OFF_WA   32768                       // half2 was[32]        128 (dead by FF)
#define OFF_Q    32896                       // float qsm[8*33]     1056 (dead by FF)
#define OFF_YS   33952                       // float ys[8*33]      1056
#define OFF_H1   35008                       // float h1s[8*132]    4224
#define OFF_B1   39232                       // float b1s[128]       512
#define OFF_B2   39744                       // float b2s[32]        128
#define OFF_G2   39872                       // float g2s[32]        128
#define OFF_BE2  40000                       // float be2s[32]       128
#define OFF_VS   40128                       // float vsh[8*33]     1056
#define SMEM_FUSED 41184

// deg-3 poly tanh on FMA pipe: t = x*(1 - x^2/3)
#define POLY3(dst, q, k, wa)                                        \
    {                                                               \
        __half2 xp = __hadd2((q), (k));                             \
        __half2 x2 = __hmul2(xp, xp);                               \
        __half2 tp = __hfma2(x2, ca2, one2);                        \
        (dst) = __hfma2((wa), __hmul2(xp, tp), (dst));              \
    }

__global__ void __launch_bounds__(128) k_fused(const float* __restrict__ x,
                                               float* __restrict__ a_out,
                                               const float* __restrict__ Wa,
                                               const float* __restrict__ ba,
                                               const float* __restrict__ g1,
                                               const float* __restrict__ be1,
                                               const float* __restrict__ W1,
                                               const float* __restrict__ b1,
                                               const float* __restrict__ W2,
                                               const float* __restrict__ b2,
                                               const float* __restrict__ g2,
                                               const float* __restrict__ be2,
                                               float* __restrict__ y2) {
    extern __shared__ char dyn[];
    __half2* khs  = (__half2*)(dyn + OFF_K);    // [32][128]
    __half2* es   = (__half2*)(dyn + OFF_E);    // [8][512]
    __half2* was  = (__half2*)(dyn + OFF_WA);
    float* qsm  = (float*)(dyn + OFF_Q);
    float* W1T  = (float*)(dyn + OFF_K);        // FF overlay
    float* W2p  = (float*)(dyn + OFF_K + 16512);
    float* ys   = (float*)(dyn + OFF_YS);
    float* h1s  = (float*)(dyn + OFF_H1);
    float* b1s  = (float*)(dyn + OFF_B1);
    float* b2s  = (float*)(dyn + OFF_B2);
    float* g2s  = (float*)(dyn + OFF_G2);
    float* be2s = (float*)(dyn + OFF_BE2);
    float* vsh  = (float*)(dyn + OFF_VS);

    unsigned dyn_su = (unsigned)__cvta_generic_to_shared(dyn);

    int b  = blockIdx.x >> 7;
    int t0 = (blockIdx.x & 127) * 8;
    int tid = threadIdx.x, w = tid >> 5, lane = tid & 31;
    int rA = 2 * w, rB = rA + 1;
    int tA = t0 + rA, tB = t0 + rB;
    size_t rowA = (size_t)b * Tt + tA, rowB = (size_t)b * Tt + tB;

    // ---- staging ----
    for (int i = tid; i < 8 * Uu; i += 128) {
        int r = i >> 5, u = i & 31;
        qsm[r * 33 + u] = g_qp[((size_t)b * Tt + t0 + r) * Uu + u];
    }
    if (tid < Uu) was[tid] = __float2half2_rn(Wa[tid]);
    if (tid < Hh) b1s[tid] = b1[tid];
    if (tid < Cc) { b2s[tid] = b2[tid]; g2s[tid] = g2[tid]; be2s[tid] = be2[tid]; }
    __syncthreads();

    __half2 qA[Uu], qB[Uu];
    #pragma unroll
    for (int u = 0; u < Uu; u++) {
        qA[u] = __float2half2_rn(qsm[rA * 33 + u]);
        qB[u] = __float2half2_rn(qsm[rB * 33 + u]);
    }
    __half2 ba2  = __float2half2_rn(ba[0]);
    __half2 z2   = __float2half2_rn(0.f);
    __half2 one2 = __float2half2_rn(1.f);
    __half2 ca2  = __float2half2_rn(-1.f / 3.f);

    const uint4* kb4 = (const uint4*)g_kh_u + (size_t)b * (Uu * Tt / 8);

    // ---- Phase A: e for rows rA,rB into smem es (no max tracking) ----
    for (int ch = 0; ch < NCHK; ch++) {
        __syncthreads();
        #pragma unroll
        for (int k = 0; k < 8; k++) {
            int idx = tid + k * 128;
            int r = idx >> 5, g = idx & 31;
            ((uint4*)khs)[idx] = kb4[r * 128 + ch * 32 + g];
        }
        __syncthreads();

        #pragma unroll
        for (int jt = 0; jt < 4; jt++) {
            int pj = jt * 32 + lane;
            __half2 a0 = z2, a1 = z2, b0 = z2, b1h = z2;
            #pragma unroll
            for (int u = 0; u < Uu; u += 4) {
                __half2 k0 = khs[u * 128 + pj];
                __half2 k1 = khs[(u + 1) * 128 + pj];
                __half2 k2 = khs[(u + 2) * 128 + pj];
                __half2 k3 = khs[(u + 3) * 128 + pj];
                a0 = __hfma2(was[u], tanh2(__hadd2(qA[u], k0)), a0);
                b0 = __hfma2(was[u], tanh2(__hadd2(qB[u], k0)), b0);
                POLY3(a1, qA[u + 1], k1, was[u + 1]);
                POLY3(b1h, qB[u + 1], k1, was[u + 1]);
                if (u < 24) {
                    a0 = __hfma2(was[u + 2], tanh2(__hadd2(qA[u + 2], k2)), a0);
                    b0 = __hfma2(was[u + 2], tanh2(__hadd2(qB[u + 2], k2)), b0);
                } else {
                    POLY3(a1, qA[u + 2], k2, was[u + 2]);
                    POLY3(b1h, qB[u + 2], k2, was[u + 2]);
                }
                POLY3(a1, qA[u + 3], k3, was[u + 3]);
                POLY3(b1h, qB[u + 3], k3, was[u + 3]);
            }
            es[rA * 512 + ch * 128 + pj] = __hadd2(__hadd2(a0, a1), ba2);
            es[rB * 512 + ch * 128 + pj] = __hadd2(__hadd2(b0, b1h), ba2);
        }
    }

    // ---- p-pass: exp in place (lane-private uint4 slots), sum s ----
    float sA = 0.f, sB = 0.f;
    {
        uint4* esA4 = (uint4*)(es + rA * 512);
        uint4* esB4 = (uint4*)(es + rB * 512);
        #pragma unroll
        for (int g = 0; g < 4; g++) {
            uint4 ea = esA4[g * 32 + lane], eb = esB4[g * 32 + lane];
            unsigned eua[4] = {ea.x, ea.y, ea.z, ea.w};
            unsigned eub[4] = {eb.x, eb.y, eb.z, eb.w};
            #pragma unroll
            for (int r = 0; r < 4; r++) {
                float2 fa = __half22float2(u2h2(eua[r]));
                float2 fb = __half22float2(u2h2(eub[r]));
                float pax = __expf(fa.x), pay = __expf(fa.y);
                float pbx = __expf(fb.x), pby = __expf(fb.y);
                sA += pax + pay; sB += pbx + pby;
                eua[r] = h22u(__floats2half2_rn(pax, pay));
                eub[r] = h22u(__floats2half2_rn(pbx, pby));
            }
            esA4[g * 32 + lane] = make_uint4(eua[0], eua[1], eua[2], eua[3]);
            esB4[g * 32 + lane] = make_uint4(eub[0], eub[1], eub[2], eub[3]);
        }
    }
    #pragma unroll
    for (int off = 16; off; off >>= 1) {
        sA += __shfl_xor_sync(0xffffffffu, sA, off);
        sB += __shfl_xor_sync(0xffffffffu, sB, off);
    }
    float invA = 1.f / (sA + 1e-5f);
    float invB = 1.f / (sB + 1e-5f);
    __syncwarp();   // p fully visible within warp before cross-lane a-read

    // ---- a-write: a = p * inv straight from smem ----
    {
        float* arowA = a_out + rowA * Tt;
        float* arowB = a_out + rowB * Tt;
        const unsigned* esA = (const unsigned*)(es + rA * 512);
        const unsigned* esB = (const unsigned*)(es + rB * 512);
        #pragma unroll
        for (int q = 0; q < 16; q++) {
            int idx = q * 32 + lane;
            float2 fa = __half22float2(u2h2(esA[idx]));
            float2 fb = __half22float2(u2h2(esB[idx]));
            ((float2*)arowA)[idx] = make_float2(fa.x * invA, fa.y * invA);
            ((float2*)arowB)[idx] = make_float2(fb.x * invB, fb.y * invB);
        }
    }

    // ---- Phase B: v = p @ x^T via mma.sync, f32 accum ----
    // warp w covers channels 8w..8w+7 (n=8), all 8 rows (m, rows 8-15 dummy).
    float d0 = 0.f, d1 = 0.f, d2 = 0.f, d3 = 0.f;
    unsigned es_su = dyn_su + OFF_E;
    unsigned xb_su = dyn_su + OFF_K;
    int rsel = ((lane & 15) < 8) ? (lane & 15) : 0;      // dummy rows -> row 0
    unsigned aBase = es_su + rsel * 2048 + ((lane >> 4) ? 16u : 0u);
    int ln = lane & 15;
    unsigned bBase = xb_su + (unsigned)(8 * w + (ln & 7)) * 512 + ((ln >> 3) ? 16u : 0u);

    const uint4* xsrc = (const uint4*)g_xh_u + (size_t)b * (Cc * Tt / 8);

    for (int ch = 0; ch < NCHK; ch++) {
        __syncthreads();
        #pragma unroll
        for (int k = 0; k < 8; k++) {
            int idx = tid + k * 128;
            int r = idx >> 5, g = idx & 31;
            ((uint4*)khs)[idx] = xsrc[r * 128 + ch * 32 + g];
        }
        __syncthreads();

        #pragma unroll
        for (int ks = 0; ks < 16; ks++) {
            unsigned aAddr = aBase + (unsigned)(ch * 256 + ks * 16) * 2;
            unsigned bAddr = bBase + (unsigned)(ks * 16) * 2;
            unsigned a0, a1, a2, a3, bb0, bb1;
            asm volatile("ldmatrix.sync.aligned.m8n8.x4.shared.b16 {%0,%1,%2,%3}, [%4];"
                         : "=r"(a0), "=r"(a1), "=r"(a2), "=r"(a3) : "r"(aAddr));
            asm volatile("ldmatrix.sync.aligned.m8n8.x2.shared.b16 {%0,%1}, [%2];"
                         : "=r"(bb0), "=r"(bb1) : "r"(bAddr));
            asm volatile("mma.sync.aligned.m16n8k16.row.col.f32.f16.f16.f32 "
                         "{%0,%1,%2,%3}, {%4,%5,%6,%7}, {%8,%9}, {%0,%1,%2,%3};"
                         : "+f"(d0), "+f"(d1), "+f"(d2), "+f"(d3)
                         : "r"(a0), "r"(a1), "r"(a2), "r"(a3), "r"(bb0), "r"(bb1));
        }
    }
    // D rows 0-7 valid: lane -> v[lane/4][8w + 2(lane%4) (+1)]
    vsh[(lane >> 2) * 33 + 8 * w + 2 * (lane & 3)]     = d0;
    vsh[(lane >> 2) * 33 + 8 * w + 2 * (lane & 3) + 1] = d1;

    __syncthreads();   // vsh complete; es/khs dead -> FF weight overlay

    for (int i = tid; i < Hh * Cc; i += 128) {
        int h = i >> 5, c = i & 31;
        W1T[c * 129 + h] = W1[i];                 // W1 (H,C) row-major
        int c2 = i >> 7, h2 = i & 127;
        W2p[c2 * 129 + h2] = W2[i];               // W2 (C,H) row-major
    }

    // ---- LN1 (lane = channel) -> ys ----
    const float* xb = x + (size_t)b * Cc * Tt + (size_t)lane * Tt;
    #pragma unroll
    for (int r = 0; r < 2; r++) {
        int t = (r == 0) ? tA : tB;
        float z = xb[t] + vsh[(2 * w + r) * 33 + lane] * ((r == 0) ? invA : invB);
        float sum = z;
        #pragma unroll
        for (int off = 16; off; off >>= 1)
            sum += __shfl_xor_sync(0xffffffffu, sum, off);
        float mean = sum * (1.f / Cc);
        float d = z - mean;
        float vv = d * d;
        #pragma unroll
        for (int off = 16; off; off >>= 1)
            vv += __shfl_xor_sync(0xffffffffu, vv, off);
        float rstd = rsqrtf(vv * (1.f / Cc) + 1e-14f);
        ys[(2 * w + r) * 33 + lane] = d * rstd * g1[lane] + be1[lane];
    }
    __syncthreads();   // weights staged + ys ready

    // ---- FF (intra-warp, tokens 2w, 2w+1) ----
    int tokbase = 2 * w;
    float acc[4][2];
    #pragma unroll
    for (int k = 0; k < 4; k++) {
        float bb = b1s[lane + 32 * k];
        acc[k][0] = bb; acc[k][1] = bb;
    }
    #pragma unroll
    for (int c = 0; c < Cc; c++) {
        float yv0 = ys[tokbase * 33 + c];
        float yv1 = ys[(tokbase + 1) * 33 + c];
        #pragma unroll
        for (int k = 0; k < 4; k++) {
            float wv = W1T[c * 129 + lane + 32 * k];
            acc[k][0] += yv0 * wv;
            acc[k][1] += yv1 * wv;
        }
    }
    #pragma unroll
    for (int k = 0; k < 4; k++) {
        h1s[tokbase * 132 + lane + 32 * k]       = fmaxf(acc[k][0], 0.f);
        h1s[(tokbase + 1) * 132 + lane + 32 * k] = fmaxf(acc[k][1], 0.f);
    }
    __syncwarp();

    float a2f[2] = {0.f, 0.f};
    #pragma unroll 4
    for (int h = 0; h < Hh; h++) {
        float wv = W2p[lane * 129 + h];
        a2f[0] += h1s[tokbase * 132 + h] * wv;
        a2f[1] += h1s[(tokbase + 1) * 132 + h] * wv;
    }

    #pragma unroll
    for (int tk = 0; tk < 2; tk++) {
        int tok = tokbase + tk;
        int t = t0 + tok;
        float z = ys[tok * 33 + lane] + a2f[tk] + b2s[lane];
        float sum = z;
        #pragma unroll
        for (int off = 16; off; off >>= 1)
            sum += __shfl_xor_sync(0xffffffffu, sum, off);
        float mean = sum * (1.f / Cc);
        float d = z - mean;
        float vv = d * d;
        #pragma unroll
        for (int off = 16; off; off >>= 1)
            vv += __shfl_xor_sync(0xffffffffu, vv, off);
        float rstd = rsqrtf(vv * (1.f / Cc) + 1e-14f);
        y2[(size_t)b * Cc * Tt + (size_t)lane * Tt + t] = d * rstd * g2s[lane] + be2s[lane];
    }
}

// ---------------------------------------------------------------------------
extern "C" void kernel_launch(void* const* d_in, const int* in_sizes, int n_in,
                              void* d_out, int out_size) {
    (void)in_sizes; (void)n_in; (void)out_size;
    const float* x   = (const float*)d_in[0];
    const float* Wt  = (const float*)d_in[1];
    const float* Wx  = (const float*)d_in[2];
    const float* bh  = (const float*)d_in[3];
    const float* Wa  = (const float*)d_in[4];
    const float* ba  = (const float*)d_in[5];
    const float* g1  = (const float*)d_in[6];
    const float* be1 = (const float*)d_in[7];
    const float* W1  = (const float*)d_in[8];
    const float* b1  = (const float*)d_in[9];
    const float* W2  = (const float*)d_in[10];
    const float* b2  = (const float*)d_in[11];
    const float* g2  = (const float*)d_in[12];
    const float* be2 = (const float*)d_in[13];

    float* out = (float*)d_out;
    float* y2  = out;                    // (B,C,T) = 131072 floats
    float* a   = out + Bq * Cc * Tt;     // (B,T,T) = 4194304 floats

    cudaFuncSetAttribute(k_fused, cudaFuncAttributeMaxDynamicSharedMemorySize, SMEM_FUSED);

    k_prep <<<Bq * (Tt / 8), 256>>>(x, Wt, Wx, bh);
    k_fused<<<Bq * (Tt / 8), 128, SMEM_FUSED>>>(x, a, Wa, ba, g1, be1,
                                                W1, b1, W2, b2, g2, be2, y2);
}

// round 17
// speedup vs baseline: 1.4085x; 1.4085x over previous
#include <cuda_runtime.h>
#include <cuda_fp16.h>

#define Bq 4
#define Cc 32
#define Tt 1024
#define Uu 32
#define Hh 128
#define NCHK 4                  // 256-j chunks
#define KROW 144                // padded k-tile row stride in bytes (32 half2 + pad)

// Scratch — device globals (no allocations allowed).
__device__ float    g_qp[Bq * Tt * Uu];            // q + bh, (B,T,U) f32
__device__ unsigned g_kh_u[Bq * (Tt / 2) * Uu];    // k as f16 pairs, layout (B, pair, U)
__device__ unsigned g_xh_u[Bq * Cc * Tt / 2];      // x as f16, (B,C,T)

__device__ __forceinline__ __half2 tanh2(__half2 x) {
    unsigned xi = *reinterpret_cast<unsigned*>(&x), ri;
    asm("tanh.approx.f16x2 %0, %1;" : "=r"(ri) : "r"(xi));
    return *reinterpret_cast<__half2*>(&ri);
}
__device__ __forceinline__ __half2 u2h2(unsigned u) { return *reinterpret_cast<__half2*>(&u); }
__device__ __forceinline__ unsigned h22u(__half2 h) { return *reinterpret_cast<unsigned*>(&h); }

// ---------------------------------------------------------------------------
// k_prep: 8 tokens/block, grid = B*(T/8) = 512, 256 threads.
// Writes k in (B, pair, U) layout for the fused kernel's vector loads.
// ---------------------------------------------------------------------------
__global__ void __launch_bounds__(256) k_prep(const float* __restrict__ x,
                                              const float* __restrict__ Wt,
                                              const float* __restrict__ Wx,
                                              const float* __restrict__ bh) {
    __shared__ float xs[Cc][9];
    __shared__ float Wts[Cc][33];
    __shared__ float Wxs[Cc][33];
    __shared__ float bhs[Uu];
    __shared__ __half kts[Uu][10];

    int b  = blockIdx.x >> 7;
    int t0 = (blockIdx.x & 127) * 8;
    int tid = threadIdx.x, w = tid >> 5, lane = tid & 31;

    {
        int c = tid >> 3, tl = tid & 7;
        xs[c][tl] = x[(size_t)b * Cc * Tt + (size_t)c * Tt + t0 + tl];
    }
    for (int i = tid; i < Cc * Uu; i += 256) {
        int c = i >> 5, u = i & 31;
        Wts[c][u] = Wt[i];
        Wxs[c][u] = Wx[i];
    }
    if (tid < Uu) bhs[tid] = bh[tid];
    __syncthreads();

    {
        int tl = w, u = lane;
        float accq = bhs[u], acck = 0.f;
        #pragma unroll
        for (int c = 0; c < Cc; c++) {
            float xv = xs[c][tl];
            accq += xv * Wts[c][u];
            acck += xv * Wxs[c][u];
        }
        g_qp[((size_t)b * Tt + t0 + tl) * Uu + u] = accq;
        kts[u][tl] = __float2half(acck);
    }
    __syncthreads();

    if (tid < 128) {
        // k: (b, pair, u) layout, one half2 per thread, 128B coalesced per warp
        int u = tid & 31, p = tid >> 5;                 // p in 0..3
        __half2 kv = __halves2half2(kts[u][2 * p], kts[u][2 * p + 1]);
        g_kh_u[((size_t)b * (Tt / 2) + (t0 >> 1) + p) * Uu + u] = h22u(kv);
        // xh unchanged layout (B,C,T)
        int r = tid >> 2, g = tid & 3;
        __half* xh = (__half*)g_xh_u;
        __half2 xv = __floats2half2_rn(xs[r][2 * g], xs[r][2 * g + 1]);
        *(unsigned*)(xh + ((size_t)b * Cc + r) * Tt + t0 + 2 * g) = h22u(xv);
    }
}

// ---------------------------------------------------------------------------
// k_fused (R14 + transposed k-tile): 8 rows/block, 128 threads,
// warp w owns rows 2w, 2w+1. grid = B*(T/8) = 512.
// ---------------------------------------------------------------------------
#define OFF_K    0                           // k-tile [128 rows][144B] 18432 | x-tile[32][128] | W1T/W2p overlay
#define OFF_E    18432                       // half2 es[8][512]   16384 (e then p)
#define OFF_WA   34816                       // half2 was[32]        128
#define OFF_Q    34944                       // float qsm[8*33]     1056
#define OFF_YS   36000                       // float ys[8*33]      1056
#define OFF_H1   37056                       // float h1s[8*132]    4224
#define OFF_B1   41280                       // float b1s[128]       512
#define OFF_B2   41792                       // float b2s[32]        128
#define OFF_G2   41920                       // float g2s[32]        128
#define OFF_BE2  42048                       // float be2s[32]       128
#define SMEM_FUSED 42176

// deg-3 poly tanh on FMA pipe: t = x*(1 - x^2/3)
#define POLY3(dst, q, k, wa)                                        \
    {                                                               \
        __half2 xp = __hadd2((q), (k));                             \
        __half2 x2 = __hmul2(xp, xp);                               \
        __half2 tp = __hfma2(x2, ca2, one2);                        \
        (dst) = __hfma2((wa), __hmul2(xp, tp), (dst));              \
    }

__global__ void __launch_bounds__(128) k_fused(const float* __restrict__ x,
                                               float* __restrict__ a_out,
                                               const float* __restrict__ Wa,
                                               const float* __restrict__ ba,
                                               const float* __restrict__ g1,
                                               const float* __restrict__ be1,
                                               const float* __restrict__ W1,
                                               const float* __restrict__ b1,
                                               const float* __restrict__ W2,
                                               const float* __restrict__ b2,
                                               const float* __restrict__ g2,
                                               const float* __restrict__ be2,
                                               float* __restrict__ y2) {
    extern __shared__ char dyn[];
    char*    ktile = dyn + OFF_K;               // k: [128 rows][KROW bytes]
    __half2* xh2s  = (__half2*)(dyn + OFF_K);   // x: [32][128] half2 (Phase B)
    __half2* es    = (__half2*)(dyn + OFF_E);   // [8][512]: e then p
    __half2* was   = (__half2*)(dyn + OFF_WA);
    float* qsm  = (float*)(dyn + OFF_Q);
    float* W1T  = (float*)(dyn + OFF_K);        // FF overlay
    float* W2p  = (float*)(dyn + OFF_K + 16512);
    float* ys   = (float*)(dyn + OFF_YS);
    float* h1s  = (float*)(dyn + OFF_H1);
    float* b1s  = (float*)(dyn + OFF_B1);
    float* b2s  = (float*)(dyn + OFF_B2);
    float* g2s  = (float*)(dyn + OFF_G2);
    float* be2s = (float*)(dyn + OFF_BE2);

    int b  = blockIdx.x >> 7;
    int t0 = (blockIdx.x & 127) * 8;
    int tid = threadIdx.x, w = tid >> 5, lane = tid & 31;
    int rA = 2 * w, rB = rA + 1;
    int tA = t0 + rA, tB = t0 + rB;
    size_t rowA = (size_t)b * Tt + tA, rowB = (size_t)b * Tt + tB;

    // ---- staging ----
    for (int i = tid; i < 8 * Uu; i += 128) {
        int r = i >> 5, u = i & 31;
        qsm[r * 33 + u] = g_qp[((size_t)b * Tt + t0 + r) * Uu + u];
    }
    if (tid < Uu) was[tid] = __float2half2_rn(Wa[tid]);
    if (tid < Hh) b1s[tid] = b1[tid];
    if (tid < Cc) { b2s[tid] = b2[tid]; g2s[tid] = g2[tid]; be2s[tid] = be2[tid]; }
    __syncthreads();

    __half2 qA[Uu], qB[Uu];
    #pragma unroll
    for (int u = 0; u < Uu; u++) {
        qA[u] = __float2half2_rn(qsm[rA * 33 + u]);
        qB[u] = __float2half2_rn(qsm[rB * 33 + u]);
    }
    __half2 ba2  = __float2half2_rn(ba[0]);
    __half2 z2   = __float2half2_rn(0.f);
    __half2 one2 = __float2half2_rn(1.f);
    __half2 ca2  = __float2half2_rn(-1.f / 3.f);

    // k source: (b, pair, u) — per batch (Tt/2)*Uu unsigned = (Tt/2)*Uu/4 uint4
    const uint4* kb4T = (const uint4*)g_kh_u + (size_t)b * ((Tt / 2) * Uu / 4);

    // ---- Phase A: e for rows rA,rB into smem es ----
    for (int ch = 0; ch < NCHK; ch++) {
        __syncthreads();
        #pragma unroll
        for (int k = 0; k < 8; k++) {
            int idx = tid + k * 128;                 // 1024 uint4 per chunk
            int r = idx >> 3, g = idx & 7;           // row = pair, 8 uint4/row
            *(uint4*)(ktile + r * KROW + 16 * g) = kb4T[ch * 1024 + idx];
        }
        __syncthreads();

        #pragma unroll
        for (int jt = 0; jt < 4; jt++) {
            int pj = jt * 32 + lane;
            const char* krow = ktile + pj * KROW;
            __half2 a0 = z2, a1 = z2, b0 = z2, b1h = z2;
            #pragma unroll
            for (int ug = 0; ug < 8; ug++) {
                uint4 kv = *(const uint4*)(krow + 16 * ug);
                __half2 k0 = u2h2(kv.x), k1 = u2h2(kv.y);
                __half2 k2 = u2h2(kv.z), k3 = u2h2(kv.w);
                int u = 4 * ug;
                a0 = __hfma2(was[u], tanh2(__hadd2(qA[u], k0)), a0);
                b0 = __hfma2(was[u], tanh2(__hadd2(qB[u], k0)), b0);
                POLY3(a1, qA[u + 1], k1, was[u + 1]);
                POLY3(b1h, qB[u + 1], k1, was[u + 1]);
                if (ug < 6) {
                    a0 = __hfma2(was[u + 2], tanh2(__hadd2(qA[u + 2], k2)), a0);
                    b0 = __hfma2(was[u + 2], tanh2(__hadd2(qB[u + 2], k2)), b0);
                } else {
                    POLY3(a1, qA[u + 2], k2, was[u + 2]);
                    POLY3(b1h, qB[u + 2], k2, was[u + 2]);
                }
                POLY3(a1, qA[u + 3], k3, was[u + 3]);
                POLY3(b1h, qB[u + 3], k3, was[u + 3]);
            }
            es[rA * 512 + ch * 128 + pj] = __hadd2(__hadd2(a0, a1), ba2);
            es[rB * 512 + ch * 128 + pj] = __hadd2(__hadd2(b0, b1h), ba2);
        }
    }

    // ---- p-pass: exp in place (lane-private uint4 slots), sum s ----
    float sA = 0.f, sB = 0.f;
    {
        uint4* esA4 = (uint4*)(es + rA * 512);
        uint4* esB4 = (uint4*)(es + rB * 512);
        #pragma unroll
        for (int g = 0; g < 4; g++) {
            uint4 ea = esA4[g * 32 + lane], eb = esB4[g * 32 + lane];
            unsigned eua[4] = {ea.x, ea.y, ea.z, ea.w};
            unsigned eub[4] = {eb.x, eb.y, eb.z, eb.w};
            #pragma unroll
            for (int r = 0; r < 4; r++) {
                float2 fa = __half22float2(u2h2(eua[r]));
                float2 fb = __half22float2(u2h2(eub[r]));
                float pax = __expf(fa.x), pay = __expf(fa.y);
                float pbx = __expf(fb.x), pby = __expf(fb.y);
                sA += pax + pay; sB += pbx + pby;
                eua[r] = h22u(__floats2half2_rn(pax, pay));
                eub[r] = h22u(__floats2half2_rn(pbx, pby));
            }
            esA4[g * 32 + lane] = make_uint4(eua[0], eua[1], eua[2], eua[3]);
            esB4[g * 32 + lane] = make_uint4(eub[0], eub[1], eub[2], eub[3]);
        }
    }
    #pragma unroll
    for (int off = 16; off; off >>= 1) {
        sA += __shfl_xor_sync(0xffffffffu, sA, off);
        sB += __shfl_xor_sync(0xffffffffu, sB, off);
    }
    float invA = 1.f / (sA + 1e-5f);
    float invB = 1.f / (sB + 1e-5f);
    __syncwarp();

    // ---- a-write: a = p * inv straight from smem ----
    {
        float* arowA = a_out + rowA * Tt;
        float* arowB = a_out + rowB * Tt;
        const unsigned* esA = (const unsigned*)(es + rA * 512);
        const unsigned* esB = (const unsigned*)(es + rB * 512);
        #pragma unroll
        for (int q = 0; q < 16; q++) {
            int idx = q * 32 + lane;
            float2 fa = __half22float2(u2h2(esA[idx]));
            float2 fb = __half22float2(u2h2(esB[idx]));
            ((float2*)arowA)[idx] = make_float2(fa.x * invA, fa.y * invA);
            ((float2*)arowB)[idx] = make_float2(fb.x * invB, fb.y * invB);
        }
    }

    // ---- Phase B: v accumulation (p from smem, x-tiles) ----
    __half2 vA[Cc], vB[Cc];
    #pragma unroll
    for (int c = 0; c < Cc; c++) { vA[c] = z2; vB[c] = z2; }

    const uint4* xsrc = (const uint4*)g_xh_u + (size_t)b * (Cc * Tt / 8);

    for (int ch = 0; ch < NCHK; ch++) {
        __syncthreads();
        #pragma unroll
        for (int k = 0; k < 8; k++) {
            int idx = tid + k * 128;
            int r = idx >> 5, g = idx & 31;
            ((uint4*)xh2s)[idx] = xsrc[r * 128 + ch * 32 + g];
        }
        __syncthreads();

        uint4 ea = ((const uint4*)(es + rA * 512))[ch * 32 + lane];
        uint4 eb = ((const uint4*)(es + rB * 512))[ch * 32 + lane];
        __half2 pA[4] = {u2h2(ea.x), u2h2(ea.y), u2h2(ea.z), u2h2(ea.w)};
        __half2 pB[4] = {u2h2(eb.x), u2h2(eb.y), u2h2(eb.z), u2h2(eb.w)};
        #pragma unroll
        for (int c = 0; c < Cc; c++) {
            uint4 xv = ((const uint4*)(xh2s + c * 128))[lane];
            vA[c] = __hfma2(pA[0], u2h2(xv.x), vA[c]);
            vA[c] = __hfma2(pA[1], u2h2(xv.y), vA[c]);
            vA[c] = __hfma2(pA[2], u2h2(xv.z), vA[c]);
            vA[c] = __hfma2(pA[3], u2h2(xv.w), vA[c]);
            vB[c] = __hfma2(pB[0], u2h2(xv.x), vB[c]);
            vB[c] = __hfma2(pB[1], u2h2(xv.y), vB[c]);
            vB[c] = __hfma2(pB[2], u2h2(xv.z), vB[c]);
            vB[c] = __hfma2(pB[3], u2h2(xv.w), vB[c]);
        }
    }

    float vfA[Cc], vfB[Cc];
    #pragma unroll
    for (int c = 0; c < Cc; c++) {
        float2 fa = __half22float2(vA[c]); vfA[c] = fa.x + fa.y;
        float2 fb = __half22float2(vB[c]); vfB[c] = fb.x + fb.y;
    }

    float mineA = 0.f, mineB = 0.f;
    #pragma unroll
    for (int c = 0; c < Cc; c++) {
        float ta = vfA[c], tb = vfB[c];
        #pragma unroll
        for (int off = 16; off; off >>= 1) {
            ta += __shfl_xor_sync(0xffffffffu, ta, off);
            tb += __shfl_xor_sync(0xffffffffu, tb, off);
        }
        if (lane == c) { mineA = ta; mineB = tb; }
    }

    __syncthreads();   // es/k/x tiles dead -> FF weight overlay begins

    for (int i = tid; i < Hh * Cc; i += 128) {
        int h = i >> 5, c = i & 31;
        W1T[c * 129 + h] = W1[i];                 // W1 (H,C) row-major
        int c2 = i >> 7, h2 = i & 127;
        W2p[c2 * 129 + h2] = W2[i];               // W2 (C,H) row-major
    }

    // ---- LN1 (lane = channel) -> ys ----
    const float* xb = x + (size_t)b * Cc * Tt + (size_t)lane * Tt;
    #pragma unroll
    for (int r = 0; r < 2; r++) {
        int t = (r == 0) ? tA : tB;
        float z = xb[t] + ((r == 0) ? mineA * invA : mineB * invB);
        float sum = z;
        #pragma unroll
        for (int off = 16; off; off >>= 1)
            sum += __shfl_xor_sync(0xffffffffu, sum, off);
        float mean = sum * (1.f / Cc);
        float d = z - mean;
        float vv = d * d;
        #pragma unroll
        for (int off = 16; off; off >>= 1)
            vv += __shfl_xor_sync(0xffffffffu, vv, off);
        float rstd = rsqrtf(vv * (1.f / Cc) + 1e-14f);
        ys[(2 * w + r) * 33 + lane] = d * rstd * g1[lane] + be1[lane];
    }
    __syncthreads();   // weights staged + ys ready

    // ---- FF (intra-warp, tokens 2w, 2w+1) ----
    int tokbase = 2 * w;
    float acc[4][2];
    #pragma unroll
    for (int k = 0; k < 4; k++) {
        float bb = b1s[lane + 32 * k];
        acc[k][0] = bb; acc[k][1] = bb;
    }
    #pragma unroll
    for (int c = 0; c < Cc; c++) {
        float yv0 = ys[tokbase * 33 + c];
        float yv1 = ys[(tokbase + 1) * 33 + c];
        #pragma unroll
        for (int k = 0; k < 4; k++) {
            float wv = W1T[c * 129 + lane + 32 * k];
            acc[k][0] += yv0 * wv;
            acc[k][1] += yv1 * wv;
        }
    }
    #pragma unroll
    for (int k = 0; k < 4; k++) {
        h1s[tokbase * 132 + lane + 32 * k]       = fmaxf(acc[k][0], 0.f);
        h1s[(tokbase + 1) * 132 + lane + 32 * k] = fmaxf(acc[k][1], 0.f);
    }
    __syncwarp();

    float a2f[2] = {0.f, 0.f};
    #pragma unroll 4
    for (int h = 0; h < Hh; h++) {
        float wv = W2p[lane * 129 + h];
        a2f[0] += h1s[tokbase * 132 + h] * wv;
        a2f[1] += h1s[(tokbase + 1) * 132 + h] * wv;
    }

    #pragma unroll
    for (int tk = 0; tk < 2; tk++) {
        int tok = tokbase + tk;
        int t = t0 + tok;
        float z = ys[tok * 33 + lane] + a2f[tk] + b2s[lane];
        float sum = z;
        #pragma unroll
        for (int off = 16; off; off >>= 1)
            sum += __shfl_xor_sync(0xffffffffu, sum, off);
        float mean = sum * (1.f / Cc);
        float d = z - mean;
        float vv = d * d;
        #pragma unroll
        for (int off = 16; off; off >>= 1)
            vv += __shfl_xor_sync(0xffffffffu, vv, off);
        float rstd = rsqrtf(vv * (1.f / Cc) + 1e-14f);
        y2[(size_t)b * Cc * Tt + (size_t)lane * Tt + t] = d * rstd * g2s[lane] + be2s[lane];
    }
}

// ---------------------------------------------------------------------------
extern "C" void kernel_launch(void* const* d_in, const int* in_sizes, int n_in,
                              void* d_out, int out_size) {
    (void)in_sizes; (void)n_in; (void)out_size;
    const float* x   = (const float*)d_in[0];
    const float* Wt  = (const float*)d_in[1];
    const float* Wx  = (const float*)d_in[2];
    const float* bh  = (const float*)d_in[3];
    const float* Wa  = (const float*)d_in[4];
    const float* ba  = (const float*)d_in[5];
    const float* g1  = (const float*)d_in[6];
    const float* be1 = (const float*)d_in[7];
    const float* W1  = (const float*)d_in[8];
    const float* b1  = (const float*)d_in[9];
    const float* W2  = (const float*)d_in[10];
    const float* b2  = (const float*)d_in[11];
    const float* g2  = (const float*)d_in[12];
    const float* be2 = (const float*)d_in[13];

    float* out = (float*)d_out;
    float* y2  = out;                    // (B,C,T) = 131072 floats
    float* a   = out + Bq * Cc * Tt;     // (B,T,T) = 4194304 floats

    cudaFuncSetAttribute(k_fused, cudaFuncAttributeMaxDynamicSharedMemorySize, SMEM_FUSED);

    k_prep <<<Bq * (Tt / 8), 256>>>(x, Wt, Wx, bh);
    k_fused<<<Bq * (Tt / 8), 128, SMEM_FUSED>>>(x, a, Wa, ba, g1, be1,
                                                W1, b1, W2, b2, g2, be2, y2);
}